// round 10
// baseline (speedup 1.0000x reference)
#include <cuda_runtime.h>
#include <cuda_bf16.h>
#include <math.h>

// Problem constants (from reference)
#define NUM_POS_FEATS 64          // F
#define N_AXES 3
#define MAX_COORD 128             // SPATIAL dims are all 128
#define TABLE_ELEMS (N_AXES * MAX_COORD * NUM_POS_FEATS)   // 24576 floats = 96 KB

// Lookup table: table[(c*128 + q)*64 + f]
//   f even: sin(q_norm_c / dim_t[f]),  f odd: cos(q_norm_c / dim_t[f])
// 32B-aligned for ld.global.v8.f32.
__device__ __align__(32) float g_table[TABLE_ELEMS];

// All-fp32 table build: rel-err budget is 1e-3, fp32 sinf/cosf give ~1e-7.
__global__ void build_table_kernel(const int* __restrict__ sx,
                                   const int* __restrict__ sy,
                                   const int* __restrict__ sz) {
    int idx = blockIdx.x * blockDim.x + threadIdx.x;
    if (idx >= TABLE_ELEMS) return;
    int c   = idx / (MAX_COORD * NUM_POS_FEATS);
    int rem = idx - c * (MAX_COORD * NUM_POS_FEATS);
    int q   = rem / NUM_POS_FEATS;
    int f   = rem - q * NUM_POS_FEATS;

    int S = (c == 0) ? *sx : (c == 1) ? *sy : *sz;

    // vals = q/(S-1+eps) * 2*pi ; dim_t = 10000^(2*(f/2)/64) ; p = vals/dim_t
    float denom = (float)(S - 1) + 1.0e-06f;
    float val   = ((float)q / denom) * 6.2831853071795864769f;
    float ex    = (float)(f >> 1) * (13.287712379549449f / 32.0f);   // log2(10000)/32
    float dt    = exp2f(ex);
    float p     = val / dt;
    g_table[idx] = (f & 1) ? cosf(p) : sinf(p);
}

// 256-bit global memory ops (sm_100+/sm_103a).
__device__ __forceinline__ void ldg256_nc(const float* p, float4& a, float4& b) {
    asm volatile("ld.global.nc.v8.f32 {%0,%1,%2,%3,%4,%5,%6,%7}, [%8];"
                 : "=f"(a.x), "=f"(a.y), "=f"(a.z), "=f"(a.w),
                   "=f"(b.x), "=f"(b.y), "=f"(b.z), "=f"(b.w)
                 : "l"(p));
}
__device__ __forceinline__ void stg256_cs(float* p, const float4& a, const float4& b) {
    asm volatile("st.global.cs.v8.f32 [%0], {%1,%2,%3,%4,%5,%6,%7,%8};"
                 :: "l"(p),
                    "f"(a.x), "f"(a.y), "f"(a.z), "f"(a.w),
                    "f"(b.x), "f"(b.y), "f"(b.z), "f"(b.w)
                 : "memory");
}

// One "oct" = 8 consecutive output floats (32B). 192 floats/point = 24 octs:
//   oct g: m = g/24, r = g%24, axis c = r/8, oct-in-axis oq = r%8.
// Warp-stride unroll-4: warp owns 128 consecutive octs; lane l handles
// base+l+32*i. Each warp iteration = one fully-contiguous 1024B store burst
// (STG.256 per lane). 4 independent chains keep bytes-in-flight equal to the
// R9 unroll-8/128-bit version with half the instructions.
__global__ void __launch_bounds__(256) fill_kernel(const int* __restrict__ coords,
                                                   float* __restrict__ out,
                                                   int total_octs) {
    const unsigned warp_id = (unsigned)(blockIdx.x * (blockDim.x >> 5) + (threadIdx.x >> 5));
    const unsigned lane    = threadIdx.x & 31u;
    const unsigned base    = warp_id * 128u + lane;

#pragma unroll
    for (int i = 0; i < 4; i++) {
        unsigned g = base + (unsigned)i * 32u;
        if (g < (unsigned)total_octs) {
            unsigned m  = g / 24u;           // point index
            unsigned r  = g - m * 24u;
            unsigned c  = r >> 3;            // axis 0..2
            unsigned oq = r & 7u;            // 32B-chunk within the 64-feature block

            int q = __ldg(&coords[m * 4u + 1u + c]);   // 0..127

            const float* src = g_table + ((c * (unsigned)MAX_COORD + (unsigned)q)
                                          * (unsigned)NUM_POS_FEATS + oq * 8u);
            float4 a, b;
            ldg256_nc(src, a, b);
            stg256_cs(out + (size_t)g * 8u, a, b);
        }
    }
}

extern "C" void kernel_launch(void* const* d_in, const int* in_sizes, int n_in,
                              void* d_out, int out_size) {
    const int* coords = (const int*)d_in[0];
    const int* sx = (const int*)d_in[1];
    const int* sy = (const int*)d_in[2];
    const int* sz = (const int*)d_in[3];
    (void)n_in;

    int M = in_sizes[0] / 4;                    // number of points
    int total_octs = M * 24;                    // (M*192)/8 32B chunks

    build_table_kernel<<<(TABLE_ELEMS + 255) / 256, 256>>>(sx, sy, sz);

    // 128 octs per warp, 8 warps per block -> 1024 octs per block
    int n_blocks = (total_octs + 1023) / 1024;
    fill_kernel<<<n_blocks, 256>>>(coords, (float*)d_out, total_octs);
    (void)out_size;
}

// round 11
// speedup vs baseline: 1.0910x; 1.0910x over previous
#include <cuda_runtime.h>
#include <cuda_bf16.h>
#include <math.h>

// Problem constants (from reference)
#define NUM_POS_FEATS 64          // F
#define N_AXES 3
#define MAX_COORD 128             // SPATIAL dims are all 128
#define TABLE_ELEMS (N_AXES * MAX_COORD * NUM_POS_FEATS)   // 24576 floats = 96 KB

// Lookup table: table[(c*128 + q)*64 + f]
//   f even: sin(q_norm_c / dim_t[f]),  f odd: cos(q_norm_c / dim_t[f])
__device__ float g_table[TABLE_ELEMS];

// All-fp32 table build: rel-err budget is 1e-3, fp32 sinf/cosf give ~1e-7.
__global__ void build_table_kernel(const int* __restrict__ sx,
                                   const int* __restrict__ sy,
                                   const int* __restrict__ sz) {
    int idx = blockIdx.x * blockDim.x + threadIdx.x;
    if (idx >= TABLE_ELEMS) return;
    int c   = idx / (MAX_COORD * NUM_POS_FEATS);
    int rem = idx - c * (MAX_COORD * NUM_POS_FEATS);
    int q   = rem / NUM_POS_FEATS;
    int f   = rem - q * NUM_POS_FEATS;

    int S = (c == 0) ? *sx : (c == 1) ? *sy : *sz;

    // vals = q/(S-1+eps) * 2*pi ; dim_t = 10000^(2*(f/2)/64) ; p = vals/dim_t
    float denom = (float)(S - 1) + 1.0e-06f;
    float val   = ((float)q / denom) * 6.2831853071795864769f;
    float ex    = (float)(f >> 1) * (13.287712379549449f / 32.0f);   // log2(10000)/32
    float dt    = exp2f(ex);
    float p     = val / dt;
    g_table[idx] = (f & 1) ? cosf(p) : sinf(p);
}

// Warp-stride unroll-16: each warp owns 512 consecutive output float4s.
// Lane l handles quads base+l+32*i (i=0..15) -> every STG is a fully-coalesced
// 512B warp write; 16 independent LDG->LDG->STG chains per thread (MLP=16)
// hide the table-load latency behind the store stream.
// __stcs: output (251.6MB) exceeds L2 (126MB); evict-first avoids thrashing
// L2 against the 96KB table.
__global__ void __launch_bounds__(256) fill_kernel(const int* __restrict__ coords,
                                                   float4* __restrict__ out,
                                                   int total_quads) {
    const unsigned warp_id = (unsigned)(blockIdx.x * (blockDim.x >> 5) + (threadIdx.x >> 5));
    const unsigned lane    = threadIdx.x & 31u;
    const unsigned base    = warp_id * 512u + lane;

    const float4* tbl = reinterpret_cast<const float4*>(g_table);

#pragma unroll
    for (int i = 0; i < 16; i++) {
        unsigned g = base + (unsigned)i * 32u;
        if (g < (unsigned)total_quads) {
            unsigned m  = g / 48u;           // point index
            unsigned r  = g - m * 48u;
            unsigned c  = r >> 4;            // axis 0..2
            unsigned fq = r & 15u;           // float4 within the 64-feature block

            int q = __ldg(&coords[m * 4u + 1u + c]);   // 0..127

            float4 v = tbl[(c * (unsigned)MAX_COORD + (unsigned)q) * 16u + fq];
            __stcs(&out[g], v);              // streaming store, evict-first
        }
    }
}

extern "C" void kernel_launch(void* const* d_in, const int* in_sizes, int n_in,
                              void* d_out, int out_size) {
    const int* coords = (const int*)d_in[0];
    const int* sx = (const int*)d_in[1];
    const int* sy = (const int*)d_in[2];
    const int* sz = (const int*)d_in[3];
    (void)n_in;

    int M = in_sizes[0] / 4;                    // number of points
    int total_quads = M * 48;                   // (M*192)/4 float4s

    build_table_kernel<<<(TABLE_ELEMS + 255) / 256, 256>>>(sx, sy, sz);

    // 512 quads per warp, 8 warps per block -> 4096 quads per block
    int n_blocks = (total_quads + 4095) / 4096;
    fill_kernel<<<n_blocks, 256>>>(coords, (float4*)d_out, total_quads);
    (void)out_size;
}

// round 12
// speedup vs baseline: 1.1047x; 1.0125x over previous
#include <cuda_runtime.h>
#include <cuda_bf16.h>
#include <math.h>

// Problem constants (from reference)
#define NUM_POS_FEATS 64          // F
#define N_AXES 3
#define MAX_COORD 128             // SPATIAL dims are all 128
#define TABLE_ELEMS (N_AXES * MAX_COORD * NUM_POS_FEATS)   // 24576 floats = 96 KB

// Lookup table: table[(c*128 + q)*64 + f]
//   f even: sin(q_norm_c / dim_t[f]),  f odd: cos(q_norm_c / dim_t[f])
__device__ float g_table[TABLE_ELEMS];

// All-fp32 table build: rel-err budget is 1e-3, fp32 sinf/cosf give ~1e-7.
__global__ void build_table_kernel(const int* __restrict__ sx,
                                   const int* __restrict__ sy,
                                   const int* __restrict__ sz) {
    int idx = blockIdx.x * blockDim.x + threadIdx.x;
    if (idx >= TABLE_ELEMS) return;
    int c   = idx / (MAX_COORD * NUM_POS_FEATS);
    int rem = idx - c * (MAX_COORD * NUM_POS_FEATS);
    int q   = rem / NUM_POS_FEATS;
    int f   = rem - q * NUM_POS_FEATS;

    int S = (c == 0) ? *sx : (c == 1) ? *sy : *sz;

    // vals = q/(S-1+eps) * 2*pi ; dim_t = 10000^(2*(f/2)/64) ; p = vals/dim_t
    float denom = (float)(S - 1) + 1.0e-06f;
    float val   = ((float)q / denom) * 6.2831853071795864769f;
    float ex    = (float)(f >> 1) * (13.287712379549449f / 32.0f);   // log2(10000)/32
    float dt    = exp2f(ex);
    float p     = val / dt;
    g_table[idx] = (f & 1) ? cosf(p) : sinf(p);
}

// Shared body: warp-stride unroll-8 (R9 optimum: best of MLP {4,8,16}).
// Each warp owns 256 consecutive output float4s; lane l handles quads
// base+l+32*i (i=0..7): every STG is a fully-coalesced 512B warp write and
// the 8 chains are independent (MLP=8). __stcs because the 251.6MB output
// exceeds L2 (126MB) — evict-first avoids thrashing the 96KB table.
template <bool GUARDED>
__device__ __forceinline__ void fill_body(const int* __restrict__ coords,
                                          float4* __restrict__ out,
                                          unsigned total_quads) {
    const unsigned warp_id = (unsigned)(blockIdx.x * (blockDim.x >> 5) + (threadIdx.x >> 5));
    const unsigned lane    = threadIdx.x & 31u;
    const unsigned base    = warp_id * 256u + lane;

    const float4* tbl = reinterpret_cast<const float4*>(g_table);

#pragma unroll
    for (int i = 0; i < 8; i++) {
        unsigned g = base + (unsigned)i * 32u;
        if (!GUARDED || g < total_quads) {
            unsigned m  = g / 48u;           // point index
            unsigned r  = g - m * 48u;
            unsigned c  = r >> 4;            // axis 0..2
            unsigned fq = r & 15u;           // float4 within the 64-feature block

            int q = __ldg(&coords[m * 4u + 1u + c]);   // 0..127

            float4 v = tbl[(c * (unsigned)MAX_COORD + (unsigned)q) * 16u + fq];
            __stcs(&out[g], v);              // streaming store, evict-first
        }
    }
}

// Exact variant: grid covers total_quads exactly (total_quads % 2048 == 0).
// No per-iteration predication -> ptxas front-batches all 8 chains.
__global__ void __launch_bounds__(256) fill_kernel_exact(const int* __restrict__ coords,
                                                         float4* __restrict__ out,
                                                         unsigned total_quads) {
    fill_body<false>(coords, out, total_quads);
}

__global__ void __launch_bounds__(256) fill_kernel_guarded(const int* __restrict__ coords,
                                                           float4* __restrict__ out,
                                                           unsigned total_quads) {
    fill_body<true>(coords, out, total_quads);
}

extern "C" void kernel_launch(void* const* d_in, const int* in_sizes, int n_in,
                              void* d_out, int out_size) {
    const int* coords = (const int*)d_in[0];
    const int* sx = (const int*)d_in[1];
    const int* sy = (const int*)d_in[2];
    const int* sz = (const int*)d_in[3];
    (void)n_in;

    int M = in_sizes[0] / 4;                    // number of points
    unsigned total_quads = (unsigned)M * 48u;   // (M*192)/4 float4s

    build_table_kernel<<<(TABLE_ELEMS + 255) / 256, 256>>>(sx, sy, sz);

    // 256 quads per warp, 8 warps per block -> 2048 quads per block
    if (total_quads % 2048u == 0u) {
        int n_blocks = total_quads / 2048u;     // 7680 for the bench shape
        fill_kernel_exact<<<n_blocks, 256>>>(coords, (float4*)d_out, total_quads);
    } else {
        int n_blocks = (total_quads + 2047u) / 2048u;
        fill_kernel_guarded<<<n_blocks, 256>>>(coords, (float4*)d_out, total_quads);
    }
    (void)out_size;
}

// round 13
// speedup vs baseline: 1.1487x; 1.0398x over previous
#include <cuda_runtime.h>
#include <cuda_bf16.h>
#include <math.h>

// Problem constants (from reference)
#define NUM_POS_FEATS 64          // F
#define N_AXES 3
#define MAX_COORD 128             // SPATIAL dims are all 128
#define TABLE_ELEMS (N_AXES * MAX_COORD * NUM_POS_FEATS)   // 24576 floats = 96 KB

// Lookup table: table[(c*128 + q)*64 + f]
//   f even: sin(q_norm_c / dim_t[f]),  f odd: cos(q_norm_c / dim_t[f])
__device__ float g_table[TABLE_ELEMS];

// All-fp32 table build: rel-err budget is 1e-3, fp32 sinf/cosf give ~1e-7.
__global__ void build_table_kernel(const int* __restrict__ sx,
                                   const int* __restrict__ sy,
                                   const int* __restrict__ sz) {
    int idx = blockIdx.x * blockDim.x + threadIdx.x;
    if (idx >= TABLE_ELEMS) return;
    int c   = idx / (MAX_COORD * NUM_POS_FEATS);
    int rem = idx - c * (MAX_COORD * NUM_POS_FEATS);
    int q   = rem / NUM_POS_FEATS;
    int f   = rem - q * NUM_POS_FEATS;

    int S = (c == 0) ? *sx : (c == 1) ? *sy : *sz;

    // vals = q/(S-1+eps) * 2*pi ; dim_t = 10000^(2*(f/2)/64) ; p = vals/dim_t
    float denom = (float)(S - 1) + 1.0e-06f;
    float val   = ((float)q / denom) * 6.2831853071795864769f;
    float ex    = (float)(f >> 1) * (13.287712379549449f / 32.0f);   // log2(10000)/32
    float dt    = exp2f(ex);
    float p     = val / dt;
    g_table[idx] = (f & 1) ? cosf(p) : sinf(p);
}

// Warp-stride unroll-8, two-phase schedule: ALL 8 table loads issue before
// ANY store (max MLP_p1 / front-batched LDGs), then 8 back-to-back STG.128s.
// Each warp owns 256 consecutive output float4s; lane l handles quads
// base+l+32*i: every STG is a fully-coalesced 512B warp write. __stcs
// because the 251.6MB output exceeds L2 (126MB) — evict-first avoids
// thrashing L2 against the 96KB table. Exact grid: no predication.
__global__ void __launch_bounds__(256) fill_kernel_exact(const int* __restrict__ coords,
                                                         float4* __restrict__ out) {
    const unsigned warp_id = (unsigned)(blockIdx.x * (blockDim.x >> 5) + (threadIdx.x >> 5));
    const unsigned lane    = threadIdx.x & 31u;
    const unsigned base    = warp_id * 256u + lane;

    const float4* tbl = reinterpret_cast<const float4*>(g_table);

    float4 v[8];

    // Phase 1: gather (8 independent coord LDGs -> 8 independent table LDG.128s)
#pragma unroll
    for (int i = 0; i < 8; i++) {
        unsigned g  = base + (unsigned)i * 32u;
        unsigned m  = g / 48u;           // point index
        unsigned r  = g - m * 48u;
        unsigned c  = r >> 4;            // axis 0..2
        unsigned fq = r & 15u;           // float4 within the 64-feature block

        int q = __ldg(&coords[m * 4u + 1u + c]);   // 0..127
        v[i] = tbl[(c * (unsigned)MAX_COORD + (unsigned)q) * 16u + fq];
    }

    // Phase 2: 8 back-to-back streaming stores (no load stalls interleaved)
#pragma unroll
    for (int i = 0; i < 8; i++) {
        __stcs(&out[base + (unsigned)i * 32u], v[i]);
    }
}

// Guarded fallback for shapes not divisible by 2048 quads.
__global__ void __launch_bounds__(256) fill_kernel_guarded(const int* __restrict__ coords,
                                                           float4* __restrict__ out,
                                                           unsigned total_quads) {
    const unsigned warp_id = (unsigned)(blockIdx.x * (blockDim.x >> 5) + (threadIdx.x >> 5));
    const unsigned lane    = threadIdx.x & 31u;
    const unsigned base    = warp_id * 256u + lane;

    const float4* tbl = reinterpret_cast<const float4*>(g_table);

#pragma unroll
    for (int i = 0; i < 8; i++) {
        unsigned g = base + (unsigned)i * 32u;
        if (g < total_quads) {
            unsigned m  = g / 48u;
            unsigned r  = g - m * 48u;
            unsigned c  = r >> 4;
            unsigned fq = r & 15u;
            int q = __ldg(&coords[m * 4u + 1u + c]);
            float4 v = tbl[(c * (unsigned)MAX_COORD + (unsigned)q) * 16u + fq];
            __stcs(&out[g], v);
        }
    }
}

extern "C" void kernel_launch(void* const* d_in, const int* in_sizes, int n_in,
                              void* d_out, int out_size) {
    const int* coords = (const int*)d_in[0];
    const int* sx = (const int*)d_in[1];
    const int* sy = (const int*)d_in[2];
    const int* sz = (const int*)d_in[3];
    (void)n_in;

    int M = in_sizes[0] / 4;                    // number of points
    unsigned total_quads = (unsigned)M * 48u;   // (M*192)/4 float4s

    build_table_kernel<<<(TABLE_ELEMS + 255) / 256, 256>>>(sx, sy, sz);

    // 256 quads per warp, 8 warps per block -> 2048 quads per block
    if (total_quads % 2048u == 0u) {
        int n_blocks = total_quads / 2048u;     // 7680 for the bench shape
        fill_kernel_exact<<<n_blocks, 256>>>(coords, (float4*)d_out);
    } else {
        int n_blocks = (total_quads + 2047u) / 2048u;
        fill_kernel_guarded<<<n_blocks, 256>>>(coords, (float4*)d_out, total_quads);
    }
    (void)out_size;
}